// round 10
// baseline (speedup 1.0000x reference)
#include <cuda_runtime.h>
#include <cstddef>

// ---------------- problem constants ----------------
#define N_EMB 250000
#define D     128
#define N_IDX 65536
#define ROWS_PER_WARP 4          // N_EMB % 4 == 0

static constexpr float LR  = 1e-3f;
static constexpr float B1  = 0.9f;
static constexpr float B2  = 0.999f;
static constexpr float EPS = 1e-8f;

// ---------------- scratch (static device globals; zero-initialized) ----------
// g_head[row] = (occurrence index + 1) of most recent toucher, 0 = untouched.
// g_next[occ] = previous head at insertion time (chain link), 0 terminates.
// k_update self-cleans g_head back to 0, so every launch (and every graph
// replay) starts from the identical all-zero state.
__device__ __align__(16) int g_head[N_EMB];
__device__ int g_next[N_IDX];

// ---------------- helpers ----------------
__device__ __forceinline__ float adam_std(float g, float m, float p,
                                          float c1, float invd2) {
    float mn = B1 * m + (1.0f - B1) * g;
    float pn = B2 * p + (1.0f - B2) * g * g;
    return c1 * mn / (sqrtf(pn * invd2) + EPS);
}

// ---------------- cold path: touched row (23% of rows) -----------------------
// __noinline__ keeps its register pressure off the hot streaming path.
__device__ __noinline__ void process_touched(
    int row, int lane, int head, float4 e,
    const float* __restrict__ grad,
    const float* __restrict__ stepv,
    const float* __restrict__ mem,
    const float* __restrict__ pw,
    float*       __restrict__ out) {
    size_t base = (size_t)row * D + (size_t)lane * 4;

    // walk the occurrence chain, summing grads (avg chain length ~1.26)
    float4 gs = make_float4(0.f, 0.f, 0.f, 0.f);
    int c = 0;
    int occ = head - 1;
    #pragma unroll 1
    while (true) {
        const float4* gp =
            reinterpret_cast<const float4*>(grad + (size_t)occ * D + lane * 4);
        int nxt = g_next[occ];          // uniform load, overlaps with gp load
        float4 g = __ldcs(gp);
        gs.x += g.x; gs.y += g.y; gs.z += g.z; gs.w += g.w;
        c++;
        if (nxt == 0) break;
        occ = nxt - 1;
    }
    float inv = 1.0f / (float)c;
    gs.x *= inv; gs.y *= inv; gs.z *= inv; gs.w *= inv;

    float4 m = __ldcs(reinterpret_cast<const float4*>(mem + base));
    float4 p = __ldcs(reinterpret_cast<const float4*>(pw  + base));
    float  s = stepv[row] + 1.0f;

    float d1 = 1.0f - powf(B1, s);
    float d2 = 1.0f - powf(B2, s);
    float c1    = LR / d1;
    float invd2 = 1.0f / d2;

    float4 o;
    o.x = e.x - adam_std(gs.x, m.x, p.x, c1, invd2);
    o.y = e.y - adam_std(gs.y, m.y, p.y, c1, invd2);
    o.z = e.z - adam_std(gs.z, m.z, p.z, c1, invd2);
    o.w = e.w - adam_std(gs.w, m.w, p.w, c1, invd2);

    if (lane == 0) g_head[row] = 0;     // self-clean for next replay
    __stcs(reinterpret_cast<float4*>(out + base), o);
}

// ---------------- kernels ----------------

// 1) build per-row occurrence chains with atomicExch (int, cheap).
__global__ void k_chain(const int* __restrict__ idx) {
    int i = blockIdx.x * blockDim.x + threadIdx.x;
    if (i >= N_IDX) return;
    int row = __ldcs(idx + i);
    int old = atomicExch(&g_head[row], i + 1);
    g_next[i] = old;               // 0 terminates the chain
}

// 2) monolithic fused update. One warp per 4 rows; front-batched loads for MLP.
//    launch_bounds(256, 6) -> <=42 regs -> 48 warps/SM theoretical.
__global__ void __launch_bounds__(256, 6)
k_update(const float* __restrict__ grad,
         const float* __restrict__ emb,
         const float* __restrict__ stepv,
         const float* __restrict__ mem,
         const float* __restrict__ pw,
         float*       __restrict__ out) {
    int w    = (blockIdx.x * blockDim.x + threadIdx.x) >> 5;
    int lane = threadIdx.x & 31;
    int r0   = w * ROWS_PER_WARP;
    if (r0 >= N_EMB) return;       // N_EMB % 4 == 0 -> all 4 rows valid

    size_t b0 = (size_t)r0 * D + (size_t)lane * 4;

    // front-batch: 4 emb chunks + one int4 covering all 4 heads (r0 % 4 == 0)
    int4 h = *reinterpret_cast<const int4*>(g_head + r0);
    float4 e0 = __ldcs(reinterpret_cast<const float4*>(emb + b0));
    float4 e1 = __ldcs(reinterpret_cast<const float4*>(emb + b0 + D));
    float4 e2 = __ldcs(reinterpret_cast<const float4*>(emb + b0 + 2 * D));
    float4 e3 = __ldcs(reinterpret_cast<const float4*>(emb + b0 + 3 * D));

    // hot path: store copies immediately as each e arrives
    if (h.x == 0) __stcs(reinterpret_cast<float4*>(out + b0),         e0);
    if (h.y == 0) __stcs(reinterpret_cast<float4*>(out + b0 + D),     e1);
    if (h.z == 0) __stcs(reinterpret_cast<float4*>(out + b0 + 2 * D), e2);
    if (h.w == 0) __stcs(reinterpret_cast<float4*>(out + b0 + 3 * D), e3);

    // cold path: touched rows via ABI call (register isolation)
    if (h.x != 0) process_touched(r0,     lane, h.x, e0, grad, stepv, mem, pw, out);
    if (h.y != 0) process_touched(r0 + 1, lane, h.y, e1, grad, stepv, mem, pw, out);
    if (h.z != 0) process_touched(r0 + 2, lane, h.z, e2, grad, stepv, mem, pw, out);
    if (h.w != 0) process_touched(r0 + 3, lane, h.w, e3, grad, stepv, mem, pw, out);
}

// ---------------- launch ----------------
extern "C" void kernel_launch(void* const* d_in, const int* in_sizes, int n_in,
                              void* d_out, int out_size) {
    const int*   idx   = (const int*)  d_in[0];
    const float* grad  = (const float*)d_in[1];
    const float* emb   = (const float*)d_in[2];
    const float* stepv = (const float*)d_in[3];
    const float* mem   = (const float*)d_in[4];
    const float* pw    = (const float*)d_in[5];
    float* out = (float*)d_out;

    const int N_WARPS    = N_EMB / ROWS_PER_WARP;      // 62500
    const int ROW_BLOCKS = (N_WARPS + 7) / 8;          // 8 warps / block

    k_chain<<<(N_IDX + 255) / 256, 256>>>(idx);
    k_update<<<ROW_BLOCKS, 256>>>(grad, emb, stepv, mem, pw, out);
}

// round 11
// speedup vs baseline: 1.0024x; 1.0024x over previous
#include <cuda_runtime.h>
#include <cstddef>

// ---------------- problem constants ----------------
#define N_EMB 250000
#define D     128
#define N_IDX 65536
#define ROWS_PER_WARP 4          // N_EMB % 4 == 0

static constexpr float LR  = 1e-3f;
static constexpr float B1  = 0.9f;
static constexpr float B2  = 0.999f;
static constexpr float EPS = 1e-8f;

// ---------------- scratch (static device globals; zero-initialized) ----------
// g_head[row] = (occurrence index + 1) of most recent toucher, 0 = untouched.
// g_next[occ] = previous head at insertion time (chain link), 0 terminates.
// k_update self-cleans g_head back to 0, so every launch (and every graph
// replay) starts from the identical all-zero state.
__device__ __align__(16) int g_head[N_EMB];
__device__ int g_next[N_IDX];

// ---------------- helpers ----------------
__device__ __forceinline__ float adam_std(float g, float m, float p,
                                          float c1, float invd2) {
    float mn = B1 * m + (1.0f - B1) * g;
    float pn = B2 * p + (1.0f - B2) * g * g;
    return c1 * mn / (sqrtf(pn * invd2) + EPS);
}

// ---------------- cold path: touched row (23% of rows) -----------------------
// __noinline__ keeps its register pressure off the hot streaming path.
__device__ __noinline__ void process_touched(
    int row, int lane, int head, float4 e,
    const float* __restrict__ grad,
    const float* __restrict__ stepv,
    const float* __restrict__ mem,
    const float* __restrict__ pw,
    float*       __restrict__ out) {
    size_t base = (size_t)row * D + (size_t)lane * 4;

    // walk the occurrence chain, summing grads (avg chain length ~1.26)
    float4 gs = make_float4(0.f, 0.f, 0.f, 0.f);
    int c = 0;
    int occ = head - 1;
    #pragma unroll 1
    while (true) {
        const float4* gp =
            reinterpret_cast<const float4*>(grad + (size_t)occ * D + lane * 4);
        int nxt = g_next[occ];          // uniform load, overlaps with gp load
        float4 g = __ldcs(gp);
        gs.x += g.x; gs.y += g.y; gs.z += g.z; gs.w += g.w;
        c++;
        if (nxt == 0) break;
        occ = nxt - 1;
    }
    float inv = 1.0f / (float)c;
    gs.x *= inv; gs.y *= inv; gs.z *= inv; gs.w *= inv;

    float4 m = __ldcs(reinterpret_cast<const float4*>(mem + base));
    float4 p = __ldcs(reinterpret_cast<const float4*>(pw  + base));
    float  s = stepv[row] + 1.0f;

    float d1 = 1.0f - powf(B1, s);
    float d2 = 1.0f - powf(B2, s);
    float c1    = LR / d1;
    float invd2 = 1.0f / d2;

    float4 o;
    o.x = e.x - adam_std(gs.x, m.x, p.x, c1, invd2);
    o.y = e.y - adam_std(gs.y, m.y, p.y, c1, invd2);
    o.z = e.z - adam_std(gs.z, m.z, p.z, c1, invd2);
    o.w = e.w - adam_std(gs.w, m.w, p.w, c1, invd2);

    if (lane == 0) g_head[row] = 0;     // self-clean for next replay
    __stcs(reinterpret_cast<float4*>(out + base), o);
}

// ---------------- kernels ----------------

// 1) build per-row occurrence chains with atomicExch (int, cheap).
__global__ void k_chain(const int* __restrict__ idx) {
    int i = blockIdx.x * blockDim.x + threadIdx.x;
    if (i >= N_IDX) return;
    int row = __ldcs(idx + i);
    int old = atomicExch(&g_head[row], i + 1);
    g_next[i] = old;               // 0 terminates the chain
}

// 2) monolithic fused update. One warp per 4 rows; front-batched loads for MLP.
//    launch_bounds(256, 6) -> <=42 regs -> 48 warps/SM theoretical.
__global__ void __launch_bounds__(256, 6)
k_update(const float* __restrict__ grad,
         const float* __restrict__ emb,
         const float* __restrict__ stepv,
         const float* __restrict__ mem,
         const float* __restrict__ pw,
         float*       __restrict__ out) {
    int w    = (blockIdx.x * blockDim.x + threadIdx.x) >> 5;
    int lane = threadIdx.x & 31;
    int r0   = w * ROWS_PER_WARP;
    if (r0 >= N_EMB) return;       // N_EMB % 4 == 0 -> all 4 rows valid

    size_t b0 = (size_t)r0 * D + (size_t)lane * 4;

    // front-batch: 4 emb chunks + one int4 covering all 4 heads (r0 % 4 == 0)
    int4 h = *reinterpret_cast<const int4*>(g_head + r0);
    float4 e0 = __ldcs(reinterpret_cast<const float4*>(emb + b0));
    float4 e1 = __ldcs(reinterpret_cast<const float4*>(emb + b0 + D));
    float4 e2 = __ldcs(reinterpret_cast<const float4*>(emb + b0 + 2 * D));
    float4 e3 = __ldcs(reinterpret_cast<const float4*>(emb + b0 + 3 * D));

    // hot path: store copies immediately as each e arrives
    if (h.x == 0) __stcs(reinterpret_cast<float4*>(out + b0),         e0);
    if (h.y == 0) __stcs(reinterpret_cast<float4*>(out + b0 + D),     e1);
    if (h.z == 0) __stcs(reinterpret_cast<float4*>(out + b0 + 2 * D), e2);
    if (h.w == 0) __stcs(reinterpret_cast<float4*>(out + b0 + 3 * D), e3);

    // cold path: touched rows via ABI call (register isolation)
    if (h.x != 0) process_touched(r0,     lane, h.x, e0, grad, stepv, mem, pw, out);
    if (h.y != 0) process_touched(r0 + 1, lane, h.y, e1, grad, stepv, mem, pw, out);
    if (h.z != 0) process_touched(r0 + 2, lane, h.z, e2, grad, stepv, mem, pw, out);
    if (h.w != 0) process_touched(r0 + 3, lane, h.w, e3, grad, stepv, mem, pw, out);
}

// ---------------- launch ----------------
extern "C" void kernel_launch(void* const* d_in, const int* in_sizes, int n_in,
                              void* d_out, int out_size) {
    const int*   idx   = (const int*)  d_in[0];
    const float* grad  = (const float*)d_in[1];
    const float* emb   = (const float*)d_in[2];
    const float* stepv = (const float*)d_in[3];
    const float* mem   = (const float*)d_in[4];
    const float* pw    = (const float*)d_in[5];
    float* out = (float*)d_out;

    const int N_WARPS    = N_EMB / ROWS_PER_WARP;      // 62500
    const int ROW_BLOCKS = (N_WARPS + 7) / 8;          // 8 warps / block

    k_chain<<<(N_IDX + 255) / 256, 256>>>(idx);
    k_update<<<ROW_BLOCKS, 256>>>(grad, emb, stepv, mem, pw, out);
}

// round 12
// speedup vs baseline: 1.1016x; 1.0990x over previous
#include <cuda_runtime.h>
#include <cstddef>

// ---------------- problem constants ----------------
#define N_EMB 250000
#define D     128
#define N_IDX 65536
#define NG    (N_EMB / 4)            // row groups (4 rows per warp) = 62500

#define OCC_BLOCKS (N_IDX / 8)       // 8192 blocks, 8 warps each -> 65536 occ warps
#define ROW_BLOCKS ((NG + 7) / 8)    // 7813 blocks

static constexpr float LR  = 1e-3f;
static constexpr float B1  = 0.9f;
static constexpr float B2  = 0.999f;
static constexpr float EPS = 1e-8f;

// ---------------- scratch (static device globals; zero-initialized) ----------
// g_head[row] = (occurrence index + 1) of chain head (last toucher), 0 = untouched.
// g_next[occ] = previous toucher at insertion time, 0 terminates.
// k_clean restores g_head to all-zero after k_main, so every launch / graph
// replay starts from identical state.
__device__ __align__(16) int g_head[N_EMB];
__device__ int g_next[N_IDX];

// ---------------- helpers ----------------
__device__ __forceinline__ float adam_std(float g, float m, float p,
                                          float c1, float invd2) {
    float mn = B1 * m + (1.0f - B1) * g;
    float pn = B2 * p + (1.0f - B2) * g * g;
    return c1 * mn / (sqrtf(pn * invd2) + EPS);
}

// ---------------- kernels ----------------

// 1) build per-row occurrence chains with atomicExch (int, cheap).
__global__ void k_chain(const int* __restrict__ idx) {
    int i = blockIdx.x * blockDim.x + threadIdx.x;
    if (i >= N_IDX) return;
    int row = __ldcs(idx + i);
    int old = atomicExch(&g_head[row], i + 1);
    g_next[i] = old;               // 0 terminates the chain
}

// 2) warp-specialized main pass.
//    Blocks [0, OCC_BLOCKS): one warp per occurrence; chain-head warp owns the
//      row and does the full Adam update with all loads front-batched.
//    Blocks [OCC_BLOCKS, ...): one warp per 4 rows; copies untouched rows only.
__global__ void __launch_bounds__(256)
k_main(const int*   __restrict__ idx,
       const float* __restrict__ grad,
       const float* __restrict__ emb,
       const float* __restrict__ stepv,
       const float* __restrict__ mem,
       const float* __restrict__ pw,
       float*       __restrict__ out) {
    int lane = threadIdx.x & 31;

    if (blockIdx.x < OCC_BLOCKS) {
        // ---------- occurrence warp: one warp per traced id ----------
        int w = (blockIdx.x * blockDim.x + threadIdx.x) >> 5;  // 0..N_IDX-1
        int row = idx[w];                 // broadcast
        if (g_head[row] != w + 1) return; // only the chain head owns the row

        size_t base = (size_t)row * D + (size_t)lane * 4;

        // front-batch: 6 independent loads -> one DRAM round trip (len-1 chains)
        float4 e  = __ldcs(reinterpret_cast<const float4*>(emb + base));
        float4 m  = __ldcs(reinterpret_cast<const float4*>(mem + base));
        float4 p  = __ldcs(reinterpret_cast<const float4*>(pw  + base));
        float  s  = stepv[row] + 1.0f;
        float4 gs = __ldcs(reinterpret_cast<const float4*>(
                        grad + (size_t)w * D + (size_t)lane * 4));
        int nxt   = g_next[w];

        int c = 1;
        #pragma unroll 1
        while (nxt != 0) {                // rare: dup rows only (~11% of owners)
            int occ = nxt - 1;
            float4 g = __ldcs(reinterpret_cast<const float4*>(
                           grad + (size_t)occ * D + (size_t)lane * 4));
            nxt = g_next[occ];
            gs.x += g.x; gs.y += g.y; gs.z += g.z; gs.w += g.w;
            c++;
        }
        float inv = 1.0f / (float)c;
        gs.x *= inv; gs.y *= inv; gs.z *= inv; gs.w *= inv;

        float d1 = 1.0f - powf(B1, s);
        float d2 = 1.0f - powf(B2, s);
        float c1    = LR / d1;
        float invd2 = 1.0f / d2;

        float4 o;
        o.x = e.x - adam_std(gs.x, m.x, p.x, c1, invd2);
        o.y = e.y - adam_std(gs.y, m.y, p.y, c1, invd2);
        o.z = e.z - adam_std(gs.z, m.z, p.z, c1, invd2);
        o.w = e.w - adam_std(gs.w, m.w, p.w, c1, invd2);
        __stcs(reinterpret_cast<float4*>(out + base), o);
    } else {
        // ---------- row warp: copy untouched rows (4 per warp) ----------
        int w = ((blockIdx.x - OCC_BLOCKS) * blockDim.x + threadIdx.x) >> 5;
        if (w >= NG) return;
        int r0 = w * 4;
        size_t b0 = (size_t)r0 * D + (size_t)lane * 4;

        int4 h = *reinterpret_cast<const int4*>(g_head + r0);  // L2-hot (1 MB)

        // predicated loads (warp-uniform per row), then predicated stores
        float4 e0, e1, e2, e3;
        if (h.x == 0) e0 = __ldcs(reinterpret_cast<const float4*>(emb + b0));
        if (h.y == 0) e1 = __ldcs(reinterpret_cast<const float4*>(emb + b0 + D));
        if (h.z == 0) e2 = __ldcs(reinterpret_cast<const float4*>(emb + b0 + 2 * D));
        if (h.w == 0) e3 = __ldcs(reinterpret_cast<const float4*>(emb + b0 + 3 * D));
        if (h.x == 0) __stcs(reinterpret_cast<float4*>(out + b0),         e0);
        if (h.y == 0) __stcs(reinterpret_cast<float4*>(out + b0 + D),     e1);
        if (h.z == 0) __stcs(reinterpret_cast<float4*>(out + b0 + 2 * D), e2);
        if (h.w == 0) __stcs(reinterpret_cast<float4*>(out + b0 + 3 * D), e3);
    }
}

// 3) restore g_head to all-zero for the next launch / graph replay.
__global__ void k_clean(const int* __restrict__ idx) {
    int i = blockIdx.x * blockDim.x + threadIdx.x;
    if (i < N_IDX) g_head[idx[i]] = 0;   // redundant writes on dups are fine
}

// ---------------- launch ----------------
extern "C" void kernel_launch(void* const* d_in, const int* in_sizes, int n_in,
                              void* d_out, int out_size) {
    const int*   idx   = (const int*)  d_in[0];
    const float* grad  = (const float*)d_in[1];
    const float* emb   = (const float*)d_in[2];
    const float* stepv = (const float*)d_in[3];
    const float* mem   = (const float*)d_in[4];
    const float* pw    = (const float*)d_in[5];
    float* out = (float*)d_out;

    k_chain<<<(N_IDX + 255) / 256, 256>>>(idx);
    k_main<<<OCC_BLOCKS + ROW_BLOCKS, 256>>>(idx, grad, emb, stepv, mem, pw, out);
    k_clean<<<(N_IDX + 255) / 256, 256>>>(idx);
}